// round 16
// baseline (speedup 1.0000x reference)
#include <cuda_runtime.h>
#include <cuda_fp16.h>
#include <cstdint>

#define N_NODES 50000
#define N_EDGES 800000
#define H1      128
#define H2      64
#define HB      1563                       // hist blocks (800000/512)
#define XB      1563                       // x-convert blocks
#define WB      96                         // W-transpose blocks
#define SCAT_B  1563                       // scatter blocks
#define GEMM1_B 782                        // layer-1 GEMM blocks (391 tiles x 2 cols)
#define SCAN_BLOCKS 49

// ---------------- scratch (no allocations allowed) ----------------
__device__ int    g_deg[N_NODES];
__device__ int    g_ptr[N_NODES + 1];
__device__ int    g_rank[N_EDGES];
__device__ int    g_srcs[N_EDGES];
__device__ int    g_bsum[64];
__device__ int    g_flag[64];
__device__ __half g_xh[N_NODES * 128];     // fp16 x
__device__ __half g_Wt1[256 * 128];        // [Wl1^T ; Wr1^T]  fp16, [n][k]
__device__ __half g_Wt2[128 * 128];        // [Wl2^T ; Wr2^T]  fp16, [n][k]
__device__ __half g_yh[N_NODES * H1];      // fp16 lin_l output (reused layer 2)
__device__ float  g_r1[N_NODES * H1];      // fp32 lin_r output (reused layer 2)
__device__ __half g_hh[N_NODES * H1];      // fp16 hidden h

// ---------------- PTX helpers ----------------
__device__ __forceinline__ void mma_f16(float* c, const uint32_t* a, const uint32_t* b) {
    asm volatile(
        "mma.sync.aligned.m16n8k16.row.col.f32.f16.f16.f32 "
        "{%0,%1,%2,%3}, {%4,%5,%6,%7}, {%8,%9}, {%0,%1,%2,%3};"
        : "+f"(c[0]), "+f"(c[1]), "+f"(c[2]), "+f"(c[3])
        : "r"(a[0]), "r"(a[1]), "r"(a[2]), "r"(a[3]),
          "r"(b[0]), "r"(b[1]));
}
#define LDSM_X4(r, addr) \
    asm volatile("ldmatrix.sync.aligned.m8n8.x4.shared.b16 {%0,%1,%2,%3}, [%4];" \
        : "=r"((r)[0]), "=r"((r)[1]), "=r"((r)[2]), "=r"((r)[3]) : "r"(addr))
__device__ __forceinline__ void cp16(uint32_t s, const void* g) {
    asm volatile("cp.async.cg.shared.global [%0], [%1], 16;" :: "r"(s), "l"(g));
}
__device__ __forceinline__ void cp_commit_wait() {
    asm volatile("cp.async.commit_group;");
    asm volatile("cp.async.wait_group 0;" ::: "memory");
}

// ---------------- fat prep: hist + x->fp16 + W transpose + flag zero ----------------
__global__ __launch_bounds__(512) void k_fath(const int* __restrict__ dst,
                                              const float* __restrict__ x,
                                              const float* __restrict__ Wl1,
                                              const float* __restrict__ Wr1,
                                              const float* __restrict__ Wl2,
                                              const float* __restrict__ Wr2) {
    int b = blockIdx.x, t = threadIdx.x;
    if (b < HB) {
        int e = b * 512 + t;
        if (e < N_EDGES) g_rank[e] = atomicAdd(&g_deg[dst[e]], 1);
    } else if (b < HB + XB) {
        int chunk = (b - HB) * 512 + t;
        if (chunk < N_NODES * 16) {          // 8 floats per chunk
            int i8 = chunk * 8;
            float4 v0 = *(const float4*)&x[i8];
            float4 v1 = *(const float4*)&x[i8 + 4];
            __half2 h0 = __floats2half2_rn(v0.x, v0.y);
            __half2 h1 = __floats2half2_rn(v0.z, v0.w);
            __half2 h2 = __floats2half2_rn(v1.x, v1.y);
            __half2 h3 = __floats2half2_rn(v1.z, v1.w);
            *(uint4*)&g_xh[i8] = make_uint4(*(uint32_t*)&h0, *(uint32_t*)&h1,
                                            *(uint32_t*)&h2, *(uint32_t*)&h3);
        }
    } else {
        if (b == HB + XB && t < 64) g_flag[t] = 0;   // reset scan flags each call
        int i = (b - HB - XB) * 512 + t;
        if (i < 256 * 128) {
            int n = i >> 7, k = i & 127;
            float w = (n < 128) ? Wl1[k * 128 + n] : Wr1[k * 128 + (n - 128)];
            g_Wt1[i] = __float2half_rn(w);
        } else {
            int j = i - 256 * 128;
            if (j < 128 * 128) {
                int n = j >> 7, k = j & 127;
                float w = (n < 64) ? Wl2[k * 64 + n] : Wr2[k * 64 + (n - 64)];
                g_Wt2[j] = __float2half_rn(w);
            }
        }
    }
}

// ---------------- single-launch scan with PARALLEL lookback ----------------
__global__ __launch_bounds__(1024) void k_scan() {
    __shared__ int s[1024];
    __shared__ int off_s;
    const int t = threadIdx.x, b = blockIdx.x;
    const int i = b * 1024 + t;
    int val = 0;
    if (i < N_NODES) {
        val = g_deg[i];
        g_deg[i] = 0;                      // self-zero for next call's histogram
    }
    s[t] = val;
    if (t == 0) off_s = 0;
    __syncthreads();
#pragma unroll
    for (int off = 1; off < 1024; off <<= 1) {
        int v = (t >= off) ? s[t - off] : 0;
        __syncthreads();
        s[t] += v;
        __syncthreads();
    }
    if (t == 1023) {
        g_bsum[b] = s[1023];
        __threadfence();
        atomicExch(&g_flag[b], 1);
    }
    if (t < b) {
        while (atomicAdd(&g_flag[t], 0) == 0) {}
        atomicAdd(&off_s, atomicAdd(&g_bsum[t], 0));
    }
    __syncthreads();
    if (i < N_NODES) g_ptr[i] = off_s + s[t] - val;
    if (i == 0) g_ptr[N_NODES] = N_EDGES;
}

// ---------------- GEMM body (R12, unchanged) ----------------
template <int M_OUT>
__device__ __forceinline__ void gemm_body(__half* smh,
                                          int row0, int cw,
                                          const __half* __restrict__ A,
                                          const __half* __restrict__ Wt,
                                          __half* __restrict__ Y,
                                          float* __restrict__ R) {
    const int tid = threadIdx.x;
    uint32_t sbase = (uint32_t)__cvta_generic_to_shared(smh);
    const uint32_t sA = sbase;
    const uint32_t sW = sbase + 128 * 272;

    for (int i = tid; i < 2048; i += 512) {
        int r = i >> 4, c = i & 15;
        int gr = row0 + r;
        uint32_t d = sA + r * 272 + c * 16;
        if (gr < N_NODES) cp16(d, &A[(size_t)gr * 128 + c * 8]);
        else *(uint4*)(smh + (r * 136 + c * 8)) = make_uint4(0, 0, 0, 0);
    }
    for (int i = tid; i < 2048; i += 512) {
        int j = i >> 4, c = i & 15;
        int srcrow = cw + ((j < 64) ? j : j + M_OUT - 64);
        cp16(sW + j * 272 + c * 16, &Wt[(size_t)srcrow * 128 + c * 8]);
    }
    cp_commit_wait();
    __syncthreads();

    const int wid  = tid >> 5;
    const int lane = tid & 31;
    const int wr0  = (wid & 3) * 32;
    const int wc0  = (wid >> 2) * 32;
    const int lrow = lane & 7;

    const uint32_t aBase = sA + (uint32_t)((wr0 + lrow + ((lane >> 3) & 1) * 8) * 272
                                           + ((lane >> 4) * 8) * 2);
    const uint32_t bBase = sW + (uint32_t)((wc0 + lrow + ((lane >> 4) & 1) * 8) * 272
                                           + (((lane >> 3) & 1) * 8) * 2);

    float acc[2][4][4];
#pragma unroll
    for (int mt = 0; mt < 2; mt++)
#pragma unroll
        for (int nt = 0; nt < 4; nt++)
#pragma unroll
            for (int i = 0; i < 4; i++) acc[mt][nt][i] = 0.f;

#pragma unroll
    for (int ks = 0; ks < 8; ks++) {
        uint32_t a0[4], a1[4], b0[4], b1[4];
        LDSM_X4(a0, aBase + ks * 32);
        LDSM_X4(a1, aBase + 16 * 272 + ks * 32);
        LDSM_X4(b0, bBase + ks * 32);
        LDSM_X4(b1, bBase + 16 * 272 + ks * 32);
        mma_f16(acc[0][0], a0, &b0[0]); mma_f16(acc[0][1], a0, &b0[2]);
        mma_f16(acc[0][2], a0, &b1[0]); mma_f16(acc[0][3], a0, &b1[2]);
        mma_f16(acc[1][0], a1, &b0[0]); mma_f16(acc[1][1], a1, &b0[2]);
        mma_f16(acc[1][2], a1, &b1[0]); mma_f16(acc[1][3], a1, &b1[2]);
    }

    const int gid = lane >> 2;
    const int tig = lane & 3;
    const bool isR = (wc0 >= 64);
    const int  wcl = wc0 & 63;
#pragma unroll
    for (int mt = 0; mt < 2; mt++) {
        int r = row0 + wr0 + mt * 16 + gid;
#pragma unroll
        for (int nt = 0; nt < 4; nt++) {
            int c = cw + wcl + nt * 8 + 2 * tig;
            if (isR) {
                if (r < N_NODES)
                    *(float2*)&R[(size_t)r * M_OUT + c] =
                        make_float2(acc[mt][nt][0], acc[mt][nt][1]);
                if (r + 8 < N_NODES)
                    *(float2*)&R[(size_t)(r + 8) * M_OUT + c] =
                        make_float2(acc[mt][nt][2], acc[mt][nt][3]);
            } else {
                if (r < N_NODES)
                    *(__half2*)&Y[(size_t)r * M_OUT + c] =
                        __floats2half2_rn(acc[mt][nt][0], acc[mt][nt][1]);
                if (r + 8 < N_NODES)
                    *(__half2*)&Y[(size_t)(r + 8) * M_OUT + c] =
                        __floats2half2_rn(acc[mt][nt][2], acc[mt][nt][3]);
            }
        }
    }
}

// ---------------- fat kernel: layer-1 GEMM blocks FIRST, then scatter ----------------
__global__ __launch_bounds__(512, 2) void k_fat1(const int* __restrict__ src,
                                                 const int* __restrict__ dst,
                                                 __half* __restrict__ Y,
                                                 float* __restrict__ R) {
    extern __shared__ __half smh[];
    if (blockIdx.x < GEMM1_B) {
        int b = blockIdx.x;
        gemm_body<H1>(smh, (b >> 1) * 128, (b & 1) * 64, g_xh, g_Wt1, Y, R);
        return;
    }
    int e = (blockIdx.x - GEMM1_B) * 512 + threadIdx.x;
    if (e < N_EDGES)
        g_srcs[g_ptr[dst[e]] + g_rank[e]] = src[e];
}

// ---------------- layer-2 GEMM ----------------
__global__ __launch_bounds__(512, 2) void k_mma2(__half* __restrict__ Y,
                                                 float* __restrict__ R) {
    extern __shared__ __half smh[];
    gemm_body<H2>(smh, blockIdx.x * 128, 0, g_hh, g_Wt2, Y, R);
}

// ---------------- gather-mean aggregation: two nodes/warp, 8 edges in flight ----------------
template <int COLS, bool RELU, typename OUT_T>
__global__ __launch_bounds__(256) void k_agg(const __half* __restrict__ y,
                                             const float* __restrict__ r,
                                             const float* __restrict__ bias,
                                             OUT_T* __restrict__ out) {
    const int gwarp = (blockIdx.x * blockDim.x + threadIdx.x) >> 5;
    if (gwarp >= N_NODES / 2) return;
    const int lane = threadIdx.x & 31;
    const int half = lane >> 4;
    const int hl   = lane & 15;
    const int node = gwarp * 2 + half;

    const int p0 = g_ptr[node];
    const int p1 = g_ptr[node + 1];
    const float inv = 1.0f / (float)max(p1 - p0, 1);
    const __half2 hz = __float2half2_rn(0.0f);
    constexpr uint32_t ROWB = COLS * 2;

    if (COLS == 128) {
        const char* yb = (const char*)y + hl * 16;
        float af0 = 0.f, af1 = 0.f, af2 = 0.f, af3 = 0.f;
        float af4 = 0.f, af5 = 0.f, af6 = 0.f, af7 = 0.f;
        int j = p0;
        // ---- 8 edges per iteration: two independent groups of 4 ----
        for (; j + 8 <= p1; j += 8) {
            uint32_t of[8];
#pragma unroll
            for (int q = 0; q < 8; q++)
                of[q] = (uint32_t)__ldg(&g_srcs[j + q]) * ROWB;
            uint4 u[8];
#pragma unroll
            for (int q = 0; q < 8; q++)
                u[q] = __ldg((const uint4*)(yb + of[q]));
            // group A = edges 0..3, group B = edges 4..7 (each <=4 fp16 adds)
            __half2 a_s0 = __hadd2(__hadd2(*(__half2*)&u[0].x, *(__half2*)&u[1].x),
                                   __hadd2(*(__half2*)&u[2].x, *(__half2*)&u[3].x));
            __half2 a_s1 = __hadd2(__hadd2(*(__half2*)&u[0].y, *(__half2*)&u[1].y),
                                   __hadd2(*(__half2*)&u[2].y, *(__half2*)&u[3].y));
            __half2 a_s2 = __hadd2(__hadd2(*(__half2*)&u[0].z, *(__half2*)&u[1].z),
                                   __hadd2(*(__half2*)&u[2].z, *(__half2*)&u[3].z));
            __half2 a_s3 = __hadd2(__hadd2(*(__half2*)&u[0].w, *(__half2*)&u[1].w),
                                   __hadd2(*(__half2*)&u[2].w, *(__half2*)&u[3].w));
            __half2 b_s0 = __hadd2(__hadd2(*(__half2*)&u[4].x, *(__half2*)&u[5].x),
                                   __hadd2(*(__half2*)&u[6].x, *(__half2*)&u[7].x));
            __half2 b_s1 = __hadd2(__hadd2(*(__half2*)&u[4].y, *(__half2*)&u[5].y),
                                   __hadd2(*(__half2*)&u[6].y, *(__half2*)&u[7].y));
            __half2 b_s2 = __hadd2(__hadd2(*(__half2*)&u[4].z, *(__half2*)&u[5].z),
                                   __hadd2(*(__half2*)&u[6].z, *(__half2*)&u[7].z));
            __half2 b_s3 = __hadd2(__hadd2(*(__half2*)&u[4].w, *(__half2*)&u[5].w),
                                   __hadd2(*(__half2*)&u[6].w, *(__half2*)&u[7].w));
            float2 f;
            f = __half22float2(a_s0); af0 += f.x; af1 += f.y;
            f = __half22float2(a_s1); af2 += f.x; af3 += f.y;
            f = __half22float2(a_s2); af4 += f.x; af5 += f.y;
            f = __half22float2(a_s3); af6 += f.x; af7 += f.y;
            f = __half22float2(b_s0); af0 += f.x; af1 += f.y;
            f = __half22float2(b_s1); af2 += f.x; af3 += f.y;
            f = __half22float2(b_s2); af4 += f.x; af5 += f.y;
            f = __half22float2(b_s3); af6 += f.x; af7 += f.y;
        }
        // ---- 4 edges ----
        if (j + 4 <= p1) {
            uint32_t o0 = (uint32_t)__ldg(&g_srcs[j])     * ROWB;
            uint32_t o1 = (uint32_t)__ldg(&g_srcs[j + 1]) * ROWB;
            uint32_t o2 = (uint32_t)__ldg(&g_srcs[j + 2]) * ROWB;
            uint32_t o3 = (uint32_t)__ldg(&g_srcs[j + 3]) * ROWB;
            uint4 u0 = __ldg((const uint4*)(yb + o0));
            uint4 u1 = __ldg((const uint4*)(yb + o1));
            uint4 u2 = __ldg((const uint4*)(yb + o2));
            uint4 u3 = __ldg((const uint4*)(yb + o3));
            __half2 s0 = __hadd2(__hadd2(*(__half2*)&u0.x, *(__half2*)&u1.x),
                                 __hadd2(*(__half2*)&u2.x, *(__half2*)&u3.x));
            __half2 s1 = __hadd2(__hadd2(*(__half2*)&u0.y, *(__half2*)&u1.y),
                                 __hadd2(*(__half2*)&u2.y, *(__half2*)&u3.y));
            __half2 s2 = __hadd2(__hadd2(*(__half2*)&u0.z, *(__half2*)&u1.z),
                                 __hadd2(*(__half2*)&u2.z, *(__half2*)&u3.z));
            __half2 s3 = __hadd2(__hadd2(*(__half2*)&u0.w, *(__half2*)&u1.w),
                                 __hadd2(*(__half2*)&u2.w, *(__half2*)&u3.w));
            float2 f;
            f = __half22float2(s0); af0 += f.x; af1 += f.y;
            f = __half22float2(s1); af2 += f.x; af3 += f.y;
            f = __half22float2(s2); af4 += f.x; af5 += f.y;
            f = __half22float2(s3); af6 += f.x; af7 += f.y;
            j += 4;
        }
        // ---- tail (<4) ----
        if (j < p1) {
            __half2 t0 = hz, t1 = hz, t2 = hz, t3 = hz;
            for (; j < p1; j++) {
                uint32_t off = (uint32_t)__ldg(&g_srcs[j]) * ROWB;
                uint4 u = __ldg((const uint4*)(yb + off));
                t0 = __hadd2(t0, *(__half2*)&u.x);
                t1 = __hadd2(t1, *(__half2*)&u.y);
                t2 = __hadd2(t2, *(__half2*)&u.z);
                t3 = __hadd2(t3, *(__half2*)&u.w);
            }
            float2 f;
            f = __half22float2(t0); af0 += f.x; af1 += f.y;
            f = __half22float2(t1); af2 += f.x; af3 += f.y;
            f = __half22float2(t2); af4 += f.x; af5 += f.y;
            f = __half22float2(t3); af6 += f.x; af7 += f.y;
        }
        const int c = hl * 8;
        float4 rb0 = *(const float4*)&r[(size_t)node * 128 + c];
        float4 rb1 = *(const float4*)&r[(size_t)node * 128 + c + 4];
        float4 bb0 = __ldg((const float4*)&bias[c]);
        float4 bb1 = __ldg((const float4*)&bias[c + 4]);
        float o0 = fmaf(af0, inv, bb0.x + rb0.x);
        float o1 = fmaf(af1, inv, bb0.y + rb0.y);
        float o2 = fmaf(af2, inv, bb0.z + rb0.z);
        float o3 = fmaf(af3, inv, bb0.w + rb0.w);
        float o4 = fmaf(af4, inv, bb1.x + rb1.x);
        float o5 = fmaf(af5, inv, bb1.y + rb1.y);
        float o6 = fmaf(af6, inv, bb1.z + rb1.z);
        float o7 = fmaf(af7, inv, bb1.w + rb1.w);
        if (RELU) {
            o0 = fmaxf(o0, 0.f); o1 = fmaxf(o1, 0.f);
            o2 = fmaxf(o2, 0.f); o3 = fmaxf(o3, 0.f);
            o4 = fmaxf(o4, 0.f); o5 = fmaxf(o5, 0.f);
            o6 = fmaxf(o6, 0.f); o7 = fmaxf(o7, 0.f);
        }
        if (sizeof(OUT_T) == 2) {
            __half2 h0 = __floats2half2_rn(o0, o1);
            __half2 h1 = __floats2half2_rn(o2, o3);
            __half2 h2 = __floats2half2_rn(o4, o5);
            __half2 h3 = __floats2half2_rn(o6, o7);
            *(uint4*)&((__half*)out)[(size_t)node * 128 + c] =
                make_uint4(*(uint32_t*)&h0, *(uint32_t*)&h1,
                           *(uint32_t*)&h2, *(uint32_t*)&h3);
        } else {
            *(float4*)&((float*)out)[(size_t)node * 128 + c] =
                make_float4(o0, o1, o2, o3);
            *(float4*)&((float*)out)[(size_t)node * 128 + c + 4] =
                make_float4(o4, o5, o6, o7);
        }
    } else {   // COLS == 64
        const char* yb = (const char*)y + hl * 8;
        float af0 = 0.f, af1 = 0.f, af2 = 0.f, af3 = 0.f;
        int j = p0;
        for (; j + 8 <= p1; j += 8) {
            uint32_t of[8];
#pragma unroll
            for (int q = 0; q < 8; q++)
                of[q] = (uint32_t)__ldg(&g_srcs[j + q]) * ROWB;
            uint2 u[8];
#pragma unroll
            for (int q = 0; q < 8; q++)
                u[q] = __ldg((const uint2*)(yb + of[q]));
            __half2 a_s0 = __hadd2(__hadd2(*(__half2*)&u[0].x, *(__half2*)&u[1].x),
                                   __hadd2(*(__half2*)&u[2].x, *(__half2*)&u[3].x));
            __half2 a_s1 = __hadd2(__hadd2(*(__half2*)&u[0].y, *(__half2*)&u[1].y),
                                   __hadd2(*(__half2*)&u[2].y, *(__half2*)&u[3].y));
            __half2 b_s0 = __hadd2(__hadd2(*(__half2*)&u[4].x, *(__half2*)&u[5].x),
                                   __hadd2(*(__half2*)&u[6].x, *(__half2*)&u[7].x));
            __half2 b_s1 = __hadd2(__hadd2(*(__half2*)&u[4].y, *(__half2*)&u[5].y),
                                   __hadd2(*(__half2*)&u[6].y, *(__half2*)&u[7].y));
            float2 f;
            f = __half22float2(a_s0); af0 += f.x; af1 += f.y;
            f = __half22float2(a_s1); af2 += f.x; af3 += f.y;
            f = __half22float2(b_s0); af0 += f.x; af1 += f.y;
            f = __half22float2(b_s1); af2 += f.x; af3 += f.y;
        }
        if (j + 4 <= p1) {
            uint32_t o0 = (uint32_t)__ldg(&g_srcs[j])     * ROWB;
            uint32_t o1 = (uint32_t)__ldg(&g_srcs[j + 1]) * ROWB;
            uint32_t o2 = (uint32_t)__ldg(&g_srcs[j + 2]) * ROWB;
            uint32_t o3 = (uint32_t)__ldg(&g_srcs[j + 3]) * ROWB;
            uint2 u0 = __ldg((const uint2*)(yb + o0));
            uint2 u1 = __ldg((const uint2*)(yb + o1));
            uint2 u2 = __ldg((const uint2*)(yb + o2));
            uint2 u3 = __ldg((const uint2*)(yb + o3));
            __half2 s0 = __hadd2(__hadd2(*(__half2*)&u0.x, *(__half2*)&u1.x),
                                 __hadd2(*(__half2*)&u2.x, *(__half2*)&u3.x));
            __half2 s1 = __hadd2(__hadd2(*(__half2*)&u0.y, *(__half2*)&u1.y),
                                 __hadd2(*(__half2*)&u2.y, *(__half2*)&u3.y));
            float2 f;
            f = __half22float2(s0); af0 += f.x; af1 += f.y;
            f = __half22float2(s1); af2 += f.x; af3 += f.y;
            j += 4;
        }
        if (j < p1) {
            __half2 t0 = hz, t1 = hz;
            for (; j < p1; j++) {
                uint32_t off = (uint32_t)__ldg(&g_srcs[j]) * ROWB;
                uint2 u = __ldg((const uint2*)(yb + off));
                t0 = __hadd2(t0, *(__half2*)&u.x);
                t1 = __hadd2(t1, *(__half2*)&u.y);
            }
            float2 f;
            f = __half22float2(t0); af0 += f.x; af1 += f.y;
            f = __half22float2(t1); af2 += f.x; af3 += f.y;
        }
        const int c = hl * 4;
        float4 rb = *(const float4*)&r[(size_t)node * 64 + c];
        float4 bb = __ldg((const float4*)&bias[c]);
        float o0 = fmaf(af0, inv, bb.x + rb.x);
        float o1 = fmaf(af1, inv, bb.y + rb.y);
        float o2 = fmaf(af2, inv, bb.z + rb.z);
        float o3 = fmaf(af3, inv, bb.w + rb.w);
        if (RELU) {
            o0 = fmaxf(o0, 0.f); o1 = fmaxf(o1, 0.f);
            o2 = fmaxf(o2, 0.f); o3 = fmaxf(o3, 0.f);
        }
        if (sizeof(OUT_T) == 2) {
            __half2 h0 = __floats2half2_rn(o0, o1);
            __half2 h1 = __floats2half2_rn(o2, o3);
            *(uint2*)&((__half*)out)[(size_t)node * 64 + c] =
                make_uint2(*(uint32_t*)&h0, *(uint32_t*)&h1);
        } else {
            *(float4*)&((float*)out)[(size_t)node * 64 + c] =
                make_float4(o0, o1, o2, o3);
        }
    }
}

// ---------------- launch ----------------
extern "C" void kernel_launch(void* const* d_in, const int* in_sizes, int n_in,
                              void* d_out, int out_size) {
    const float* x   = (const float*)d_in[0];
    const float* Wl1 = (const float*)d_in[1];
    const float* bl1 = (const float*)d_in[2];
    const float* Wr1 = (const float*)d_in[3];
    const float* Wl2 = (const float*)d_in[4];
    const float* bl2 = (const float*)d_in[5];
    const float* Wr2 = (const float*)d_in[6];
    const int*   ei  = (const int*)d_in[7];
    const int* src = ei;
    const int* dst = ei + N_EDGES;
    float* out = (float*)d_out;

    __half *yhp, *hhp;
    float* r1p;
    cudaGetSymbolAddress((void**)&yhp, g_yh);
    cudaGetSymbolAddress((void**)&hhp, g_hh);
    cudaGetSymbolAddress((void**)&r1p, g_r1);

    constexpr int SMEM = 2 * 128 * 272;   // 69632 B
    cudaFuncSetAttribute(k_fat1,
                         cudaFuncAttributeMaxDynamicSharedMemorySize, SMEM);
    cudaFuncSetAttribute(k_mma2,
                         cudaFuncAttributeMaxDynamicSharedMemorySize, SMEM);

    // prep (hist + x->fp16 + W transpose + flag zero), then fused scan
    k_fath<<<HB + XB + WB, 512>>>(dst, x, Wl1, Wr1, Wl2, Wr2);
    k_scan<<<SCAN_BLOCKS, 1024>>>();

    // layer-1 GEMM blocks first, scatter blocks after, one launch
    k_fat1<<<GEMM1_B + SCAT_B, 512, SMEM>>>(src, dst, yhp, r1p);
    // 25000 warps, 2 nodes each -> 3125 blocks of 8 warps
    k_agg<128, true, __half><<<3125, 256>>>(yhp, r1p, bl1, hhp);

    // layer 2
    k_mma2<<<(N_NODES + 127) / 128, 512, SMEM>>>(yhp, r1p);
    k_agg<64, false, float><<<3125, 256>>>(yhp, r1p, bl2, out);
}

// round 17
// speedup vs baseline: 1.0802x; 1.0802x over previous
#include <cuda_runtime.h>
#include <cuda_fp16.h>
#include <cstdint>

#define N_NODES 50000
#define N_EDGES 800000
#define H1      128
#define H2      64
#define HB      1563                       // hist blocks (800000/512)
#define XB      1563                       // x-convert blocks
#define WB      96                         // W-transpose blocks
#define SCAT_B  1563                       // scatter blocks
#define GEMM1_B 782                        // layer-1 GEMM blocks (391 tiles x 2 cols)
#define SCAN_BLOCKS 49

// ---------------- scratch (no allocations allowed) ----------------
__device__ int    g_deg[N_NODES];
__device__ int    g_ptr[N_NODES + 1];
__device__ int    g_rank[N_EDGES];
__device__ int    g_srcs[N_EDGES];
__device__ int    g_bsum[64];
__device__ int    g_flag[64];
__device__ __half g_xh[N_NODES * 128];     // fp16 x
__device__ __half g_Wt1[256 * 128];        // [Wl1^T ; Wr1^T]  fp16, [n][k]
__device__ __half g_Wt2[128 * 128];        // [Wl2^T ; Wr2^T]  fp16, [n][k]
__device__ __half g_yh[N_NODES * H1];      // fp16 lin_l output (reused layer 2)
__device__ float  g_r1[N_NODES * H1];      // fp32 lin_r output (reused layer 2)
__device__ __half g_hh[N_NODES * H1];      // fp16 hidden h

// ---------------- PTX helpers ----------------
__device__ __forceinline__ void mma_f16(float* c, const uint32_t* a, const uint32_t* b) {
    asm volatile(
        "mma.sync.aligned.m16n8k16.row.col.f32.f16.f16.f32 "
        "{%0,%1,%2,%3}, {%4,%5,%6,%7}, {%8,%9}, {%0,%1,%2,%3};"
        : "+f"(c[0]), "+f"(c[1]), "+f"(c[2]), "+f"(c[3])
        : "r"(a[0]), "r"(a[1]), "r"(a[2]), "r"(a[3]),
          "r"(b[0]), "r"(b[1]));
}
#define LDSM_X4(r, addr) \
    asm volatile("ldmatrix.sync.aligned.m8n8.x4.shared.b16 {%0,%1,%2,%3}, [%4];" \
        : "=r"((r)[0]), "=r"((r)[1]), "=r"((r)[2]), "=r"((r)[3]) : "r"(addr))
__device__ __forceinline__ void cp16(uint32_t s, const void* g) {
    asm volatile("cp.async.cg.shared.global [%0], [%1], 16;" :: "r"(s), "l"(g));
}
__device__ __forceinline__ void cp_commit_wait() {
    asm volatile("cp.async.commit_group;");
    asm volatile("cp.async.wait_group 0;" ::: "memory");
}

// ---------------- fat prep: hist + x->fp16 + W transpose + flag zero ----------------
__global__ __launch_bounds__(512) void k_fath(const int* __restrict__ dst,
                                              const float* __restrict__ x,
                                              const float* __restrict__ Wl1,
                                              const float* __restrict__ Wr1,
                                              const float* __restrict__ Wl2,
                                              const float* __restrict__ Wr2) {
    int b = blockIdx.x, t = threadIdx.x;
    if (b < HB) {
        int e = b * 512 + t;
        if (e < N_EDGES) g_rank[e] = atomicAdd(&g_deg[dst[e]], 1);
    } else if (b < HB + XB) {
        int chunk = (b - HB) * 512 + t;
        if (chunk < N_NODES * 16) {          // 8 floats per chunk
            int i8 = chunk * 8;
            float4 v0 = *(const float4*)&x[i8];
            float4 v1 = *(const float4*)&x[i8 + 4];
            __half2 h0 = __floats2half2_rn(v0.x, v0.y);
            __half2 h1 = __floats2half2_rn(v0.z, v0.w);
            __half2 h2 = __floats2half2_rn(v1.x, v1.y);
            __half2 h3 = __floats2half2_rn(v1.z, v1.w);
            *(uint4*)&g_xh[i8] = make_uint4(*(uint32_t*)&h0, *(uint32_t*)&h1,
                                            *(uint32_t*)&h2, *(uint32_t*)&h3);
        }
    } else {
        if (b == HB + XB && t < 64) g_flag[t] = 0;   // reset scan flags each call
        int i = (b - HB - XB) * 512 + t;
        if (i < 256 * 128) {
            int n = i >> 7, k = i & 127;
            float w = (n < 128) ? Wl1[k * 128 + n] : Wr1[k * 128 + (n - 128)];
            g_Wt1[i] = __float2half_rn(w);
        } else {
            int j = i - 256 * 128;
            if (j < 128 * 128) {
                int n = j >> 7, k = j & 127;
                float w = (n < 64) ? Wl2[k * 64 + n] : Wr2[k * 64 + (n - 64)];
                g_Wt2[j] = __float2half_rn(w);
            }
        }
    }
}

// ---------------- single-launch scan with PARALLEL lookback ----------------
__global__ __launch_bounds__(1024) void k_scan() {
    __shared__ int s[1024];
    __shared__ int off_s;
    const int t = threadIdx.x, b = blockIdx.x;
    const int i = b * 1024 + t;
    int val = 0;
    if (i < N_NODES) {
        val = g_deg[i];
        g_deg[i] = 0;                      // self-zero for next call's histogram
    }
    s[t] = val;
    if (t == 0) off_s = 0;
    __syncthreads();
#pragma unroll
    for (int off = 1; off < 1024; off <<= 1) {
        int v = (t >= off) ? s[t - off] : 0;
        __syncthreads();
        s[t] += v;
        __syncthreads();
    }
    if (t == 1023) {
        g_bsum[b] = s[1023];
        __threadfence();
        atomicExch(&g_flag[b], 1);
    }
    if (t < b) {
        while (atomicAdd(&g_flag[t], 0) == 0) {}
        atomicAdd(&off_s, atomicAdd(&g_bsum[t], 0));
    }
    __syncthreads();
    if (i < N_NODES) g_ptr[i] = off_s + s[t] - val;
    if (i == 0) g_ptr[N_NODES] = N_EDGES;
}

// ---------------- GEMM body (R12, unchanged) ----------------
template <int M_OUT>
__device__ __forceinline__ void gemm_body(__half* smh,
                                          int row0, int cw,
                                          const __half* __restrict__ A,
                                          const __half* __restrict__ Wt,
                                          __half* __restrict__ Y,
                                          float* __restrict__ R) {
    const int tid = threadIdx.x;
    uint32_t sbase = (uint32_t)__cvta_generic_to_shared(smh);
    const uint32_t sA = sbase;
    const uint32_t sW = sbase + 128 * 272;

    for (int i = tid; i < 2048; i += 512) {
        int r = i >> 4, c = i & 15;
        int gr = row0 + r;
        uint32_t d = sA + r * 272 + c * 16;
        if (gr < N_NODES) cp16(d, &A[(size_t)gr * 128 + c * 8]);
        else *(uint4*)(smh + (r * 136 + c * 8)) = make_uint4(0, 0, 0, 0);
    }
    for (int i = tid; i < 2048; i += 512) {
        int j = i >> 4, c = i & 15;
        int srcrow = cw + ((j < 64) ? j : j + M_OUT - 64);
        cp16(sW + j * 272 + c * 16, &Wt[(size_t)srcrow * 128 + c * 8]);
    }
    cp_commit_wait();
    __syncthreads();

    const int wid  = tid >> 5;
    const int lane = tid & 31;
    const int wr0  = (wid & 3) * 32;
    const int wc0  = (wid >> 2) * 32;
    const int lrow = lane & 7;

    const uint32_t aBase = sA + (uint32_t)((wr0 + lrow + ((lane >> 3) & 1) * 8) * 272
                                           + ((lane >> 4) * 8) * 2);
    const uint32_t bBase = sW + (uint32_t)((wc0 + lrow + ((lane >> 4) & 1) * 8) * 272
                                           + (((lane >> 3) & 1) * 8) * 2);

    float acc[2][4][4];
#pragma unroll
    for (int mt = 0; mt < 2; mt++)
#pragma unroll
        for (int nt = 0; nt < 4; nt++)
#pragma unroll
            for (int i = 0; i < 4; i++) acc[mt][nt][i] = 0.f;

#pragma unroll
    for (int ks = 0; ks < 8; ks++) {
        uint32_t a0[4], a1[4], b0[4], b1[4];
        LDSM_X4(a0, aBase + ks * 32);
        LDSM_X4(a1, aBase + 16 * 272 + ks * 32);
        LDSM_X4(b0, bBase + ks * 32);
        LDSM_X4(b1, bBase + 16 * 272 + ks * 32);
        mma_f16(acc[0][0], a0, &b0[0]); mma_f16(acc[0][1], a0, &b0[2]);
        mma_f16(acc[0][2], a0, &b1[0]); mma_f16(acc[0][3], a0, &b1[2]);
        mma_f16(acc[1][0], a1, &b0[0]); mma_f16(acc[1][1], a1, &b0[2]);
        mma_f16(acc[1][2], a1, &b1[0]); mma_f16(acc[1][3], a1, &b1[2]);
    }

    const int gid = lane >> 2;
    const int tig = lane & 3;
    const bool isR = (wc0 >= 64);
    const int  wcl = wc0 & 63;
#pragma unroll
    for (int mt = 0; mt < 2; mt++) {
        int r = row0 + wr0 + mt * 16 + gid;
#pragma unroll
        for (int nt = 0; nt < 4; nt++) {
            int c = cw + wcl + nt * 8 + 2 * tig;
            if (isR) {
                if (r < N_NODES)
                    *(float2*)&R[(size_t)r * M_OUT + c] =
                        make_float2(acc[mt][nt][0], acc[mt][nt][1]);
                if (r + 8 < N_NODES)
                    *(float2*)&R[(size_t)(r + 8) * M_OUT + c] =
                        make_float2(acc[mt][nt][2], acc[mt][nt][3]);
            } else {
                if (r < N_NODES)
                    *(__half2*)&Y[(size_t)r * M_OUT + c] =
                        __floats2half2_rn(acc[mt][nt][0], acc[mt][nt][1]);
                if (r + 8 < N_NODES)
                    *(__half2*)&Y[(size_t)(r + 8) * M_OUT + c] =
                        __floats2half2_rn(acc[mt][nt][2], acc[mt][nt][3]);
            }
        }
    }
}

// ---------------- fat kernel: layer-1 GEMM blocks FIRST, then scatter ----------------
__global__ __launch_bounds__(512, 2) void k_fat1(const int* __restrict__ src,
                                                 const int* __restrict__ dst,
                                                 __half* __restrict__ Y,
                                                 float* __restrict__ R) {
    extern __shared__ __half smh[];
    if (blockIdx.x < GEMM1_B) {
        int b = blockIdx.x;
        gemm_body<H1>(smh, (b >> 1) * 128, (b & 1) * 64, g_xh, g_Wt1, Y, R);
        return;
    }
    int e = (blockIdx.x - GEMM1_B) * 512 + threadIdx.x;
    if (e < N_EDGES)
        g_srcs[g_ptr[dst[e]] + g_rank[e]] = src[e];
}

// ---------------- layer-2 GEMM ----------------
__global__ __launch_bounds__(512, 2) void k_mma2(__half* __restrict__ Y,
                                                 float* __restrict__ R) {
    extern __shared__ __half smh[];
    gemm_body<H2>(smh, blockIdx.x * 128, 0, g_hh, g_Wt2, Y, R);
}

// ---------------- gather-mean aggregation: two nodes/warp, pipelined offsets ----------------
// R15 structure (4 edges/iter) with next-iteration offsets computed while current
// gathers are in flight (+4 regs only).
template <int COLS, bool RELU, typename OUT_T>
__global__ __launch_bounds__(256) void k_agg(const __half* __restrict__ y,
                                             const float* __restrict__ r,
                                             const float* __restrict__ bias,
                                             OUT_T* __restrict__ out) {
    const int gwarp = (blockIdx.x * blockDim.x + threadIdx.x) >> 5;
    if (gwarp >= N_NODES / 2) return;
    const int lane = threadIdx.x & 31;
    const int half = lane >> 4;
    const int hl   = lane & 15;
    const int node = gwarp * 2 + half;

    const int p0 = g_ptr[node];
    const int p1 = g_ptr[node + 1];
    const float inv = 1.0f / (float)max(p1 - p0, 1);
    const __half2 hz = __float2half2_rn(0.0f);
    constexpr uint32_t ROWB = COLS * 2;

    if (COLS == 128) {
        const char* yb = (const char*)y + hl * 16;
        float af0 = 0.f, af1 = 0.f, af2 = 0.f, af3 = 0.f;
        float af4 = 0.f, af5 = 0.f, af6 = 0.f, af7 = 0.f;
        int j = p0;
        if (j + 4 <= p1) {
            // prologue: offsets for first iteration
            uint32_t o0 = (uint32_t)__ldg(&g_srcs[j])     * ROWB;
            uint32_t o1 = (uint32_t)__ldg(&g_srcs[j + 1]) * ROWB;
            uint32_t o2 = (uint32_t)__ldg(&g_srcs[j + 2]) * ROWB;
            uint32_t o3 = (uint32_t)__ldg(&g_srcs[j + 3]) * ROWB;
            for (; j + 4 <= p1; ) {
                uint4 u0 = __ldg((const uint4*)(yb + o0));
                uint4 u1 = __ldg((const uint4*)(yb + o1));
                uint4 u2 = __ldg((const uint4*)(yb + o2));
                uint4 u3 = __ldg((const uint4*)(yb + o3));
                j += 4;
                if (j + 4 <= p1) {   // prefetch next offsets while gathers in flight
                    o0 = (uint32_t)__ldg(&g_srcs[j])     * ROWB;
                    o1 = (uint32_t)__ldg(&g_srcs[j + 1]) * ROWB;
                    o2 = (uint32_t)__ldg(&g_srcs[j + 2]) * ROWB;
                    o3 = (uint32_t)__ldg(&g_srcs[j + 3]) * ROWB;
                }
                __half2 s0 = __hadd2(__hadd2(*(__half2*)&u0.x, *(__half2*)&u1.x),
                                     __hadd2(*(__half2*)&u2.x, *(__half2*)&u3.x));
                __half2 s1 = __hadd2(__hadd2(*(__half2*)&u0.y, *(__half2*)&u1.y),
                                     __hadd2(*(__half2*)&u2.y, *(__half2*)&u3.y));
                __half2 s2 = __hadd2(__hadd2(*(__half2*)&u0.z, *(__half2*)&u1.z),
                                     __hadd2(*(__half2*)&u2.z, *(__half2*)&u3.z));
                __half2 s3 = __hadd2(__hadd2(*(__half2*)&u0.w, *(__half2*)&u1.w),
                                     __hadd2(*(__half2*)&u2.w, *(__half2*)&u3.w));
                float2 f;
                f = __half22float2(s0); af0 += f.x; af1 += f.y;
                f = __half22float2(s1); af2 += f.x; af3 += f.y;
                f = __half22float2(s2); af4 += f.x; af5 += f.y;
                f = __half22float2(s3); af6 += f.x; af7 += f.y;
            }
        }
        if (j < p1) {                         // tail: <=3 edges in fp16 groups
            __half2 t0 = hz, t1 = hz, t2 = hz, t3 = hz;
            for (; j < p1; j++) {
                uint32_t off = (uint32_t)__ldg(&g_srcs[j]) * ROWB;
                uint4 u = __ldg((const uint4*)(yb + off));
                t0 = __hadd2(t0, *(__half2*)&u.x);
                t1 = __hadd2(t1, *(__half2*)&u.y);
                t2 = __hadd2(t2, *(__half2*)&u.z);
                t3 = __hadd2(t3, *(__half2*)&u.w);
            }
            float2 f;
            f = __half22float2(t0); af0 += f.x; af1 += f.y;
            f = __half22float2(t1); af2 += f.x; af3 += f.y;
            f = __half22float2(t2); af4 += f.x; af5 += f.y;
            f = __half22float2(t3); af6 += f.x; af7 += f.y;
        }
        const int c = hl * 8;
        float4 rb0 = *(const float4*)&r[(size_t)node * 128 + c];
        float4 rb1 = *(const float4*)&r[(size_t)node * 128 + c + 4];
        float4 bb0 = __ldg((const float4*)&bias[c]);
        float4 bb1 = __ldg((const float4*)&bias[c + 4]);
        float o0 = fmaf(af0, inv, bb0.x + rb0.x);
        float o1 = fmaf(af1, inv, bb0.y + rb0.y);
        float o2 = fmaf(af2, inv, bb0.z + rb0.z);
        float o3 = fmaf(af3, inv, bb0.w + rb0.w);
        float o4 = fmaf(af4, inv, bb1.x + rb1.x);
        float o5 = fmaf(af5, inv, bb1.y + rb1.y);
        float o6 = fmaf(af6, inv, bb1.z + rb1.z);
        float o7 = fmaf(af7, inv, bb1.w + rb1.w);
        if (RELU) {
            o0 = fmaxf(o0, 0.f); o1 = fmaxf(o1, 0.f);
            o2 = fmaxf(o2, 0.f); o3 = fmaxf(o3, 0.f);
            o4 = fmaxf(o4, 0.f); o5 = fmaxf(o5, 0.f);
            o6 = fmaxf(o6, 0.f); o7 = fmaxf(o7, 0.f);
        }
        if (sizeof(OUT_T) == 2) {
            __half2 h0 = __floats2half2_rn(o0, o1);
            __half2 h1 = __floats2half2_rn(o2, o3);
            __half2 h2 = __floats2half2_rn(o4, o5);
            __half2 h3 = __floats2half2_rn(o6, o7);
            *(uint4*)&((__half*)out)[(size_t)node * 128 + c] =
                make_uint4(*(uint32_t*)&h0, *(uint32_t*)&h1,
                           *(uint32_t*)&h2, *(uint32_t*)&h3);
        } else {
            *(float4*)&((float*)out)[(size_t)node * 128 + c] =
                make_float4(o0, o1, o2, o3);
            *(float4*)&((float*)out)[(size_t)node * 128 + c + 4] =
                make_float4(o4, o5, o6, o7);
        }
    } else {   // COLS == 64
        const char* yb = (const char*)y + hl * 8;
        float af0 = 0.f, af1 = 0.f, af2 = 0.f, af3 = 0.f;
        int j = p0;
        if (j + 4 <= p1) {
            uint32_t o0 = (uint32_t)__ldg(&g_srcs[j])     * ROWB;
            uint32_t o1 = (uint32_t)__ldg(&g_srcs[j + 1]) * ROWB;
            uint32_t o2 = (uint32_t)__ldg(&g_srcs[j + 2]) * ROWB;
            uint32_t o3 = (uint32_t)__ldg(&g_srcs[j + 3]) * ROWB;
            for (; j + 4 <= p1; ) {
                uint2 u0 = __ldg((const uint2*)(yb + o0));
                uint2 u1 = __ldg((const uint2*)(yb + o1));
                uint2 u2 = __ldg((const uint2*)(yb + o2));
                uint2 u3 = __ldg((const uint2*)(yb + o3));
                j += 4;
                if (j + 4 <= p1) {
                    o0 = (uint32_t)__ldg(&g_srcs[j])     * ROWB;
                    o1 = (uint32_t)__ldg(&g_srcs[j + 1]) * ROWB;
                    o2 = (uint32_t)__ldg(&g_srcs[j + 2]) * ROWB;
                    o3 = (uint32_t)__ldg(&g_srcs[j + 3]) * ROWB;
                }
                __half2 s0 = __hadd2(__hadd2(*(__half2*)&u0.x, *(__half2*)&u1.x),
                                     __hadd2(*(__half2*)&u2.x, *(__half2*)&u3.x));
                __half2 s1 = __hadd2(__hadd2(*(__half2*)&u0.y, *(__half2*)&u1.y),
                                     __hadd2(*(__half2*)&u2.y, *(__half2*)&u3.y));
                float2 f;
                f = __half22float2(s0); af0 += f.x; af1 += f.y;
                f = __half22float2(s1); af2 += f.x; af3 += f.y;
            }
        }
        if (j < p1) {
            __half2 t0 = hz, t1 = hz;
            for (; j < p1; j++) {
                uint32_t off = (uint32_t)__ldg(&g_srcs[j]) * ROWB;
                uint2 u = __ldg((const uint2*)(yb + off));
                t0 = __hadd2(t0, *(__half2*)&u.x);
                t1 = __hadd2(t1, *(__half2*)&u.y);
            }
            float2 f;
            f = __half22float2(t0); af0 += f.x; af1 += f.y;
            f = __half22float2(t1); af2 += f.x; af3 += f.y;
        }
        const int c = hl * 4;
        float4 rb = *(const float4*)&r[(size_t)node * 64 + c];
        float4 bb = __ldg((const float4*)&bias[c]);
        float o0 = fmaf(af0, inv, bb.x + rb.x);
        float o1 = fmaf(af1, inv, bb.y + rb.y);
        float o2 = fmaf(af2, inv, bb.z + rb.z);
        float o3 = fmaf(af3, inv, bb.w + rb.w);
        if (RELU) {
            o0 = fmaxf(o0, 0.f); o1 = fmaxf(o1, 0.f);
            o2 = fmaxf(o2, 0.f); o3 = fmaxf(o3, 0.f);
        }
        if (sizeof(OUT_T) == 2) {
            __half2 h0 = __floats2half2_rn(o0, o1);
            __half2 h1 = __floats2half2_rn(o2, o3);
            *(uint2*)&((__half*)out)[(size_t)node * 64 + c] =
                make_uint2(*(uint32_t*)&h0, *(uint32_t*)&h1);
        } else {
            *(float4*)&((float*)out)[(size_t)node * 64 + c] =
                make_float4(o0, o1, o2, o3);
        }
    }
}

// ---------------- launch ----------------
extern "C" void kernel_launch(void* const* d_in, const int* in_sizes, int n_in,
                              void* d_out, int out_size) {
    const float* x   = (const float*)d_in[0];
    const float* Wl1 = (const float*)d_in[1];
    const float* bl1 = (const float*)d_in[2];
    const float* Wr1 = (const float*)d_in[3];
    const float* Wl2 = (const float*)d_in[4];
    const float* bl2 = (const float*)d_in[5];
    const float* Wr2 = (const float*)d_in[6];
    const int*   ei  = (const int*)d_in[7];
    const int* src = ei;
    const int* dst = ei + N_EDGES;
    float* out = (float*)d_out;

    __half *yhp, *hhp;
    float* r1p;
    cudaGetSymbolAddress((void**)&yhp, g_yh);
    cudaGetSymbolAddress((void**)&hhp, g_hh);
    cudaGetSymbolAddress((void**)&r1p, g_r1);

    constexpr int SMEM = 2 * 128 * 272;   // 69632 B
    cudaFuncSetAttribute(k_fat1,
                         cudaFuncAttributeMaxDynamicSharedMemorySize, SMEM);
    cudaFuncSetAttribute(k_mma2,
                         cudaFuncAttributeMaxDynamicSharedMemorySize, SMEM);

    // prep (hist + x->fp16 + W transpose + flag zero), then fused scan
    k_fath<<<HB + XB + WB, 512>>>(dst, x, Wl1, Wr1, Wl2, Wr2);
    k_scan<<<SCAN_BLOCKS, 1024>>>();

    // layer-1 GEMM blocks first, scatter blocks after, one launch
    k_fat1<<<GEMM1_B + SCAT_B, 512, SMEM>>>(src, dst, yhp, r1p);
    k_agg<128, true, __half><<<3125, 256>>>(yhp, r1p, bl1, hhp);

    // layer 2
    k_mma2<<<(N_NODES + 127) / 128, 512, SMEM>>>(yhp, r1p);
    k_agg<64, false, float><<<3125, 256>>>(yhp, r1p, bl2, out);
}